// round 4
// baseline (speedup 1.0000x reference)
#include <cuda_runtime.h>
#include <cuda_fp16.h>

// BilateralSlice: grid (4,12,8,16,16) f32, guide (4,1,1024,1024) f32,
// out (4,12,1024,1024) f32.
//
// One CTA = one output row (b, y). y-interpolation folded into a staged fp16
// slice with CORNER DUPLICATION:
//   Sdup[x][z] = 12x half2{A_c(z),A_c(z+1)} ++ 12x half2{B_c(z),B_c(z+1)}
// where A = grid column x, B = column min(x+1,15), y-lerped in fp32.
// Per pixel: ONE base address -> 6 consecutive LDS.128 (96 B) give all corners.
// x-lerp in packed fp16 (HMUL2+HFMA2 on z-pairs), z-combine in fp32.
// z-stride 112 B => z0 in 0..7 hits 8 distinct 4-word bank groups.

#define NB 4
#define NC 12
#define DG 8
#define HG 16
#define WG 16
#define HH 1024
#define WW 1024

constexpr int ZSTRIDE = 28;            // words per z (24 data + 4 pad)
constexpr int XSTRIDE = DG * ZSTRIDE;  // 224 words per x
constexpr int THREADS = 512;

__global__ void __launch_bounds__(THREADS, 2)
bilateral_slice_kernel(const float* __restrict__ grid,
                       const float* __restrict__ guide,
                       float* __restrict__ out)
{
    __shared__ unsigned int S[WG * XSTRIDE];   // 3584 words = 14 KB

    const int b   = blockIdx.x >> 10;
    const int y   = blockIdx.x & 1023;
    const int tid = threadIdx.x;

    // ---- per-row y interpolation parameters ----
    const float iyf = (float)y * (15.0f / 1023.0f);
    const float y0f = floorf(iyf);
    const int   y0  = (int)y0f;
    const int   y1  = min(y0 + 1, HG - 1);
    const float fy  = iyf - y0f;
    const float wy0 = 1.0f - fy;

    // ---- stage y-lerped, z-paired fp16 slice with corner duplication ----
    const float* gb = grid + (size_t)b * (NC * DG * HG * WG);
    for (int i = tid; i < WG * DG * NC; i += THREADS) {
        int x  = i / (DG * NC);
        int zc = i - x * (DG * NC);
        int z  = zc / NC;
        int c  = zc - z * NC;
        int zb = min(z + 1, DG - 1);
        int b0 = (c * DG + z)  * (HG * WG);
        int b1 = (c * DG + zb) * (HG * WG);
        float va = wy0 * gb[b0 + y0 * WG + x] + fy * gb[b0 + y1 * WG + x];
        float vb = wy0 * gb[b1 + y0 * WG + x] + fy * gb[b1 + y1 * WG + x];
        __half2 h = __floats2half2_rn(va, vb);       // {v(z), v(z+1)}
        unsigned int u = *reinterpret_cast<unsigned int*>(&h);
        S[x * XSTRIDE + z * ZSTRIDE + c] = u;                     // A slot of x
        if (x > 0)
            S[(x - 1) * XSTRIDE + z * ZSTRIDE + NC + c] = u;      // B slot of x-1
        if (x == WG - 1)
            S[x * XSTRIDE + z * ZSTRIDE + NC + c] = u;            // B slot clamp
    }
    __syncthreads();

    // ---- per-pixel x/z trilinear completion, 2 px per thread ----
    const int xb = tid * 2;
    const float2 g2 = *reinterpret_cast<const float2*>(
        guide + (size_t)b * (HH * WW) + (size_t)y * WW + xb);
    float* opix = out + (size_t)b * NC * (size_t)(HH * WW)
                      + (size_t)y * WW + xb;

    float r0[NC], r1[NC];

    #pragma unroll
    for (int j = 0; j < 2; ++j) {
        const int   x  = xb + j;
        const float gv = j ? g2.y : g2.x;

        float iz  = fminf(fmaxf(gv, 0.0f), 1.0f) * (float)(DG - 1);
        float z0f = floorf(iz);
        int   z0  = (int)z0f;
        float fz  = iz - z0f;

        float ixf = (float)x * (15.0f / 1023.0f);
        float x0f = floorf(ixf);
        int   x0  = (int)x0f;
        float fx  = ixf - x0f;

        const float   wz0  = 1.0f - fz;
        const float   wz1  = fz;
        const __half2 wx0b = __float2half2_rn(1.0f - fx);
        const __half2 wx1b = __float2half2_rn(fx);

        const uint4* p = reinterpret_cast<const uint4*>(
            &S[x0 * XSTRIDE + z0 * ZSTRIDE]);
        uint4 U0 = p[0], U1 = p[1], U2 = p[2];   // A: channels 0..11
        uint4 U3 = p[3], U4 = p[4], U5 = p[5];   // B: channels 0..11

        auto lerp1 = [&](unsigned int aw, unsigned int bw) -> float {
            __half2 a = *reinterpret_cast<__half2*>(&aw);
            __half2 bb = *reinterpret_cast<__half2*>(&bw);
            __half2 t = __hfma2(bb, wx1b, __hmul2(a, wx0b));  // x-lerp, z-pair
            float2  f = __half22float2(t);
            return fmaf(wz0, f.x, wz1 * f.y);                 // z-combine fp32
        };

        float* res = j ? r1 : r0;
        res[0]  = lerp1(U0.x, U3.x);
        res[1]  = lerp1(U0.y, U3.y);
        res[2]  = lerp1(U0.z, U3.z);
        res[3]  = lerp1(U0.w, U3.w);
        res[4]  = lerp1(U1.x, U4.x);
        res[5]  = lerp1(U1.y, U4.y);
        res[6]  = lerp1(U1.z, U4.z);
        res[7]  = lerp1(U1.w, U4.w);
        res[8]  = lerp1(U2.x, U5.x);
        res[9]  = lerp1(U2.y, U5.y);
        res[10] = lerp1(U2.z, U5.z);
        res[11] = lerp1(U2.w, U5.w);
    }

    #pragma unroll
    for (int c = 0; c < NC; ++c) {
        float2 o = make_float2(r0[c], r1[c]);
        *reinterpret_cast<float2*>(opix + (size_t)c * (HH * WW)) = o;
    }
}

extern "C" void kernel_launch(void* const* d_in, const int* in_sizes, int n_in,
                              void* d_out, int out_size)
{
    const float* grid  = nullptr;
    const float* guide = nullptr;
    for (int i = 0; i < n_in; ++i) {
        if (in_sizes[i] == NB * NC * DG * HG * WG) grid  = (const float*)d_in[i];
        else if (in_sizes[i] == NB * HH * WW)      guide = (const float*)d_in[i];
    }

    dim3 gridDim(NB * HH);   // 4096 CTAs: one per (batch, row)
    bilateral_slice_kernel<<<gridDim, THREADS>>>(grid, guide, (float*)d_out);
}

// round 5
// speedup vs baseline: 2.3954x; 2.3954x over previous
#include <cuda_runtime.h>
#include <cuda_fp16.h>

// BilateralSlice: grid (4,12,8,16,16) f32, guide (4,1,1024,1024) f32,
// out (4,12,1024,1024) f32.
//
// Round-3 structure (proven: no local-mem demotion) with fp16 packed x-lerp:
//   S[x][z][c] = half2{ v_c(z), v_c(z+1) }   (y-lerped in fp32)
// Per pixel: 2 x-corner bases * 3 LDS.128 = 96 B; per channel:
//   HMUL2 + HFMA2 (x-lerp on z-pair) -> 2 cvt -> FMA+MUL (z-combine, fp32).

#define NB 4
#define NC 12
#define DG 8
#define HG 16
#define WG 16
#define HH 1024
#define WW 1024

constexpr int XSTRIDE = 100;           // words per x (12*8=96 + 4 pad)
constexpr int THREADS = 512;

__global__ void __launch_bounds__(THREADS, 2)
bilateral_slice_kernel(const float* __restrict__ grid,
                       const float* __restrict__ guide,
                       float* __restrict__ out)
{
    __shared__ unsigned int S[WG * XSTRIDE];   // half2 entries, 6.4 KB

    const int b   = blockIdx.x >> 10;
    const int y   = blockIdx.x & 1023;
    const int tid = threadIdx.x;

    // ---- per-row y interpolation parameters ----
    const float iyf = (float)y * (15.0f / 1023.0f);
    const float y0f = floorf(iyf);
    const int   y0  = (int)y0f;
    const int   y1  = min(y0 + 1, HG - 1);
    const float fy  = iyf - y0f;
    const float wy0 = 1.0f - fy;

    // ---- stage y-lerped, z-paired fp16 slice (grid is L2-resident) ----
    const float* gb = grid + (size_t)b * (NC * DG * HG * WG);
    #pragma unroll
    for (int i = tid; i < WG * DG * NC; i += THREADS) {
        int x  = i & 15;
        int zc = i >> 4;            // z*12 + c
        int z  = zc / 12;
        int c  = zc - z * 12;
        int zb = min(z + 1, DG - 1);
        const float* pz  = gb + (c * DG + z)  * (HG * WG);
        const float* pzb = gb + (c * DG + zb) * (HG * WG);
        float va = wy0 * pz[y0 * WG + x]  + fy * pz[y1 * WG + x];
        float vb = wy0 * pzb[y0 * WG + x] + fy * pzb[y1 * WG + x];
        __half2 h = __floats2half2_rn(va, vb);   // {v(z), v(z+1)}
        S[x * XSTRIDE + z * 12 + c] = *reinterpret_cast<unsigned int*>(&h);
    }
    __syncthreads();

    // ---- per-pixel x/z trilinear completion, 2 px per thread ----
    const int xb = tid * 2;
    const float2 g2 = *reinterpret_cast<const float2*>(
        guide + (size_t)b * (HH * WW) + (size_t)y * WW + xb);
    float*       opix = out + (size_t)b * NC * (size_t)(HH * WW)
                            + (size_t)y * WW + xb;

    float r0[NC], r1[NC];

    #pragma unroll
    for (int j = 0; j < 2; ++j) {
        const int   x  = xb + j;
        const float gv = j ? g2.y : g2.x;

        float iz  = __saturatef(gv) * (float)(DG - 1);
        float z0f = floorf(iz);
        int   z0  = (int)z0f;
        float fz  = iz - z0f;

        float ixf = (float)x * (15.0f / 1023.0f);
        float x0f = floorf(ixf);
        int   x0  = (int)x0f;
        int   x1  = min(x0 + 1, WG - 1);
        float fx  = ixf - x0f;

        const float   wz0  = 1.0f - fz;
        const float   wz1  = fz;
        const __half2 hwx0 = __float2half2_rn(1.0f - fx);
        const __half2 hwx1 = __float2half2_rn(fx);

        const uint4* pa = reinterpret_cast<const uint4*>(
            &S[x0 * XSTRIDE + z0 * 12]);
        const uint4* pb = reinterpret_cast<const uint4*>(
            &S[x1 * XSTRIDE + z0 * 12]);
        uint4 A0 = pa[0], A1 = pa[1], A2 = pa[2];
        uint4 B0 = pb[0], B1 = pb[1], B2 = pb[2];

        float* res = j ? r1 : r0;
        const unsigned int Aw[12] = {A0.x, A0.y, A0.z, A0.w,
                                     A1.x, A1.y, A1.z, A1.w,
                                     A2.x, A2.y, A2.z, A2.w};
        const unsigned int Bw[12] = {B0.x, B0.y, B0.z, B0.w,
                                     B1.x, B1.y, B1.z, B1.w,
                                     B2.x, B2.y, B2.z, B2.w};
        #pragma unroll
        for (int c = 0; c < NC; ++c) {
            __half2 a = *reinterpret_cast<const __half2*>(&Aw[c]);
            __half2 bb = *reinterpret_cast<const __half2*>(&Bw[c]);
            // x-lerp on the packed {z0, z1} pair in fp16
            __half2 t = __hfma2(bb, hwx1, __hmul2(a, hwx0));
            float2  f = __half22float2(t);
            // z-combine in fp32
            res[c] = fmaf(wz0, f.x, wz1 * f.y);
        }
    }

    #pragma unroll
    for (int c = 0; c < NC; ++c) {
        float2 o = make_float2(r0[c], r1[c]);
        *reinterpret_cast<float2*>(opix + (size_t)c * (HH * WW)) = o;
    }
}

extern "C" void kernel_launch(void* const* d_in, const int* in_sizes, int n_in,
                              void* d_out, int out_size)
{
    const float* grid  = nullptr;
    const float* guide = nullptr;
    for (int i = 0; i < n_in; ++i) {
        if (in_sizes[i] == NB * NC * DG * HG * WG) grid  = (const float*)d_in[i];
        else if (in_sizes[i] == NB * HH * WW)      guide = (const float*)d_in[i];
    }

    dim3 gridDim(NB * HH);   // 4096 CTAs: one per (batch, row)
    bilateral_slice_kernel<<<gridDim, THREADS>>>(grid, guide, (float*)d_out);
}

// round 6
// speedup vs baseline: 2.8031x; 1.1702x over previous
#include <cuda_runtime.h>
#include <cuda_fp16.h>

// BilateralSlice: grid (4,12,8,16,16) f32, guide (4,1,1024,1024) f32,
// out (4,12,1024,1024) f32.
//
// One CTA = (b, 4 consecutive rows). Per row, y-lerped fp16 z-pair slice:
//   S[r][x][z][c] = half2{ v_c(z), v_c(z+1) }
// Guide loads for all 4 rows prefetched before staging; one barrier per CTA.
// Inner math identical to the proven round-5 kernel.

#define NB 4
#define NC 12
#define DG 8
#define HG 16
#define WG 16
#define HH 1024
#define WW 1024

constexpr int XSTRIDE = 100;             // words per x (96 + 4 pad)
constexpr int RSTRIDE = WG * XSTRIDE;    // 1600 words per row slice
constexpr int ROWS    = 4;
constexpr int THREADS = 512;

__global__ void __launch_bounds__(THREADS, 2)
bilateral_slice_kernel(const float* __restrict__ grid,
                       const float* __restrict__ guide,
                       float* __restrict__ out)
{
    __shared__ unsigned int S[ROWS * RSTRIDE];   // 6400 words = 25.6 KB

    const int b    = blockIdx.x >> 8;
    const int rg   = blockIdx.x & 255;
    const int ybase = rg * ROWS;
    const int tid  = threadIdx.x;
    const int xb   = tid * 2;

    // ---- prefetch guide for all 4 rows (overlaps staging latency) ----
    float2 g2[ROWS];
    const float* gp = guide + (size_t)b * (HH * WW) + (size_t)ybase * WW + xb;
    #pragma unroll
    for (int r = 0; r < ROWS; ++r)
        g2[r] = *reinterpret_cast<const float2*>(gp + (size_t)r * WW);

    // ---- stage y-lerped, z-paired fp16 slices for 4 rows ----
    const float* gb = grid + (size_t)b * (NC * DG * HG * WG);
    #pragma unroll
    for (int r = 0; r < ROWS; ++r) {
        const int   y   = ybase + r;
        const float iyf = (float)y * (15.0f / 1023.0f);
        const float y0f = floorf(iyf);
        const int   y0  = (int)y0f;
        const int   y1  = min(y0 + 1, HG - 1);
        const float fy  = iyf - y0f;
        const float wy0 = 1.0f - fy;

        #pragma unroll
        for (int i = tid; i < WG * DG * NC; i += THREADS) {
            int x  = i & 15;
            int zc = i >> 4;            // z*12 + c
            int z  = zc / 12;
            int c  = zc - z * 12;
            int zb = min(z + 1, DG - 1);
            const float* pz  = gb + (c * DG + z)  * (HG * WG);
            const float* pzb = gb + (c * DG + zb) * (HG * WG);
            float va = wy0 * pz[y0 * WG + x]  + fy * pz[y1 * WG + x];
            float vb = wy0 * pzb[y0 * WG + x] + fy * pzb[y1 * WG + x];
            __half2 h = __floats2half2_rn(va, vb);   // {v(z), v(z+1)}
            S[r * RSTRIDE + x * XSTRIDE + z * 12 + c] =
                *reinterpret_cast<unsigned int*>(&h);
        }
    }
    __syncthreads();

    // ---- x-dependent math: once per thread (x fixed across rows) ----
    const float ixf0 = (float)xb * (15.0f / 1023.0f);
    const float ixf1 = (float)(xb + 1) * (15.0f / 1023.0f);
    const float x0f0 = floorf(ixf0);
    const float x0f1 = floorf(ixf1);
    const int   xA0  = (int)x0f0;
    const int   xA1  = (int)x0f1;
    const int   xB0  = min(xA0 + 1, WG - 1);
    const int   xB1  = min(xA1 + 1, WG - 1);
    const float fx0  = ixf0 - x0f0;
    const float fx1  = ixf1 - x0f1;
    const __half2 hwx0_0 = __float2half2_rn(1.0f - fx0);
    const __half2 hwx1_0 = __float2half2_rn(fx0);
    const __half2 hwx0_1 = __float2half2_rn(1.0f - fx1);
    const __half2 hwx1_1 = __float2half2_rn(fx1);

    float* obase = out + (size_t)b * NC * (size_t)(HH * WW)
                       + (size_t)ybase * WW + xb;

    #pragma unroll
    for (int r = 0; r < ROWS; ++r) {
        float r0[NC], r1[NC];

        #pragma unroll
        for (int j = 0; j < 2; ++j) {
            const float gv = j ? g2[r].y : g2[r].x;

            float iz  = __saturatef(gv) * (float)(DG - 1);
            float z0f = floorf(iz);
            int   z0  = (int)z0f;
            float fz  = iz - z0f;
            const float wz0 = 1.0f - fz;
            const float wz1 = fz;

            const int xa = j ? xA1 : xA0;
            const int xbv = j ? xB1 : xB0;
            const __half2 hwx0 = j ? hwx0_1 : hwx0_0;
            const __half2 hwx1 = j ? hwx1_1 : hwx1_0;

            const uint4* pa = reinterpret_cast<const uint4*>(
                &S[r * RSTRIDE + xa * XSTRIDE + z0 * 12]);
            const uint4* pb = reinterpret_cast<const uint4*>(
                &S[r * RSTRIDE + xbv * XSTRIDE + z0 * 12]);
            uint4 A0 = pa[0], A1 = pa[1], A2 = pa[2];
            uint4 B0 = pb[0], B1 = pb[1], B2 = pb[2];

            float* res = j ? r1 : r0;
            const unsigned int Aw[12] = {A0.x, A0.y, A0.z, A0.w,
                                         A1.x, A1.y, A1.z, A1.w,
                                         A2.x, A2.y, A2.z, A2.w};
            const unsigned int Bw[12] = {B0.x, B0.y, B0.z, B0.w,
                                         B1.x, B1.y, B1.z, B1.w,
                                         B2.x, B2.y, B2.z, B2.w};
            #pragma unroll
            for (int c = 0; c < NC; ++c) {
                __half2 a  = *reinterpret_cast<const __half2*>(&Aw[c]);
                __half2 bb = *reinterpret_cast<const __half2*>(&Bw[c]);
                __half2 t  = __hfma2(bb, hwx1, __hmul2(a, hwx0));
                float2  f  = __half22float2(t);
                res[c] = fmaf(wz0, f.x, wz1 * f.y);
            }
        }

        float* opix = obase + (size_t)r * WW;
        #pragma unroll
        for (int c = 0; c < NC; ++c) {
            float2 o = make_float2(r0[c], r1[c]);
            *reinterpret_cast<float2*>(opix + (size_t)c * (HH * WW)) = o;
        }
    }
}

extern "C" void kernel_launch(void* const* d_in, const int* in_sizes, int n_in,
                              void* d_out, int out_size)
{
    const float* grid  = nullptr;
    const float* guide = nullptr;
    for (int i = 0; i < n_in; ++i) {
        if (in_sizes[i] == NB * NC * DG * HG * WG) grid  = (const float*)d_in[i];
        else if (in_sizes[i] == NB * HH * WW)      guide = (const float*)d_in[i];
    }

    dim3 gridDim(NB * HH / ROWS);   // 1024 CTAs: one per (batch, 4-row group)
    bilateral_slice_kernel<<<gridDim, THREADS>>>(grid, guide, (float*)d_out);
}